// round 2
// baseline (speedup 1.0000x reference)
#include <cuda_runtime.h>
#include <math.h>

#define BB 16
#define TE 128
#define TD 128
#define HH 256

// Scratch (device globals — no dynamic allocation allowed)
__device__ float g_enc[BB * TE * HH];   // orthogonalized encoder
__device__ float g_was[BB * TE * HH];   // enc @ W_a
__device__ float g_uah[BB * TD * HH];   // dec @ U_a

__device__ __forceinline__ float tanh_fast(float x) {
    float y;
    asm("tanh.approx.f32 %0, %1;" : "=f"(y) : "f"(x));
    return y;
}

// ---------------------------------------------------------------------------
// Kernel 1: orthogonalize. One thread per (b,h); sequential exclusive cumsum
// over TE. Faithful to reference op order: out = x - ((x*s)/(x*x))*x.
// ---------------------------------------------------------------------------
__global__ void ortho_kernel(const float* __restrict__ enc_in) {
    int idx = blockIdx.x * blockDim.x + threadIdx.x;   // b*HH + h
    if (idx >= BB * HH) return;
    int b = idx / HH;
    int h = idx - b * HH;
    const float* src = enc_in + (size_t)b * TE * HH + h;
    float* dst = g_enc + (size_t)b * TE * HH + h;
    float s = 0.0f;
    #pragma unroll 4
    for (int t = 0; t < TE; t++) {
        float x = src[(size_t)t * HH];
        float num = x * s;
        float den = x * x;
        float o = x - (num / den) * x;   // t=0: num=0 -> o=x
        dst[(size_t)t * HH] = o;
        s += x;
    }
}

// ---------------------------------------------------------------------------
// Kernel 2: batched SGEMM.  z=0: g_was = g_enc @ W ;  z=1: g_uah = dec @ U
// M=2048, N=256, K=256. 64x64 tile, BK=16, 256 threads, 4x4 per-thread tile.
// ---------------------------------------------------------------------------
#define GBM 64
#define GBN 64
#define GBK 16
__global__ void gemm_batch_kernel(const float* __restrict__ dec,
                                  const float* __restrict__ W,
                                  const float* __restrict__ U) {
    const float* A;
    const float* Bm;
    float* C;
    if (blockIdx.z == 0) { A = g_enc; Bm = W; C = g_was; }
    else                 { A = dec;   Bm = U; C = g_uah; }

    const int M = BB * TE;   // 2048
    const int N = HH;        // 256
    const int K = HH;        // 256

    __shared__ float As[GBK][GBM];
    __shared__ float Bs[GBK][GBN];

    int tid = threadIdx.x;
    int tx = tid % 16;        // col group
    int ty = tid / 16;        // row group
    int row0 = blockIdx.y * GBM;
    int col0 = blockIdx.x * GBN;

    float acc[4][4] = {};

    for (int k0 = 0; k0 < K; k0 += GBK) {
        // load A tile 64x16 (transposed into As[k][m])
        #pragma unroll
        for (int i = tid; i < GBM * GBK; i += 256) {
            int r = i / GBK, c = i % GBK;
            As[c][r] = A[(size_t)(row0 + r) * K + k0 + c];
        }
        // load B tile 16x64
        #pragma unroll
        for (int i = tid; i < GBK * GBN; i += 256) {
            int r = i / GBN, c = i % GBN;
            Bs[r][c] = Bm[(size_t)(k0 + r) * N + col0 + c];
        }
        __syncthreads();

        #pragma unroll
        for (int k = 0; k < GBK; k++) {
            float a[4], bv[4];
            #pragma unroll
            for (int m = 0; m < 4; m++) a[m] = As[k][ty * 4 + m];
            #pragma unroll
            for (int n = 0; n < 4; n++) bv[n] = Bs[k][tx * 4 + n];
            #pragma unroll
            for (int m = 0; m < 4; m++)
                #pragma unroll
                for (int n = 0; n < 4; n++)
                    acc[m][n] = fmaf(a[m], bv[n], acc[m][n]);
        }
        __syncthreads();
    }

    #pragma unroll
    for (int m = 0; m < 4; m++)
        #pragma unroll
        for (int n = 0; n < 4; n++)
            C[(size_t)(row0 + ty * 4 + m) * N + col0 + tx * 4 + n] = acc[m][n];
}

// ---------------------------------------------------------------------------
// Kernel 3: fused energy + softmax + context.
// One block per (d, b). 256 threads = 8 warps.
//   Phase B: warp w computes energies e = w, w+8, ... (16 each);
//            lane covers h = lane + 32*i, i<8; shfl-reduce.
//   Phase C: softmax over TE=128 energies.
//   Phase D: c[h] = sum_e p[e] * enc[b,e,h], thread per h.
// ---------------------------------------------------------------------------
__global__ void attn_kernel(const float* __restrict__ Va,
                            float* __restrict__ c_out,
                            float* __restrict__ e_out) {
    int d = blockIdx.x;
    int b = blockIdx.y;
    int tid = threadIdx.x;
    int lane = tid & 31;
    int wid = tid >> 5;

    __shared__ float uah_s[HH];
    __shared__ float V_s[HH];
    __shared__ float en_s[TE];
    __shared__ float p_s[TE];
    __shared__ float red[8];

    uah_s[tid] = g_uah[((size_t)b * TD + d) * HH + tid];
    V_s[tid] = Va[tid];
    __syncthreads();

    const float* wasb = g_was + (size_t)b * TE * HH;

    // ---- Phase B: energies ----
    #pragma unroll 1
    for (int e = wid; e < TE; e += 8) {
        const float* wrow = wasb + (size_t)e * HH;
        float acc = 0.0f;
        #pragma unroll
        for (int i = 0; i < 8; i++) {
            int h = lane + 32 * i;
            float a = wrow[h] + uah_s[h];
            acc = fmaf(tanh_fast(a), V_s[h], acc);
        }
        #pragma unroll
        for (int o = 16; o > 0; o >>= 1)
            acc += __shfl_xor_sync(0xffffffffu, acc, o);
        if (lane == 0) en_s[e] = acc;
    }
    __syncthreads();

    // ---- Phase C: softmax over TE ----
    float v = (tid < TE) ? en_s[tid] : -INFINITY;

    // block max (8 warps)
    float m = v;
    #pragma unroll
    for (int o = 16; o > 0; o >>= 1)
        m = fmaxf(m, __shfl_xor_sync(0xffffffffu, m, o));
    if (lane == 0) red[wid] = m;
    __syncthreads();
    if (tid == 0) {
        float mm = red[0];
        #pragma unroll
        for (int i = 1; i < 8; i++) mm = fmaxf(mm, red[i]);
        red[0] = mm;
    }
    __syncthreads();
    m = red[0];
    __syncthreads();   // protect red[0] before reuse

    float p = (tid < TE) ? __expf(v - m) : 0.0f;
    float s = p;
    #pragma unroll
    for (int o = 16; o > 0; o >>= 1)
        s += __shfl_xor_sync(0xffffffffu, s, o);
    if (lane == 0) red[wid] = s;
    __syncthreads();
    if (tid == 0) {
        float ss = 0.0f;
        #pragma unroll
        for (int i = 0; i < 8; i++) ss += red[i];
        red[0] = ss;
    }
    __syncthreads();
    float tot = red[0];

    if (tid < TE) {
        float pn = p / tot;
        p_s[tid] = pn;
        e_out[((size_t)b * TD + d) * TE + tid] = pn;
    }
    __syncthreads();

    // ---- Phase D: context c[h] = sum_e p[e] * enc[b,e,h] ----
    const float* encb = g_enc + (size_t)b * TE * HH;
    float acc = 0.0f;
    #pragma unroll 8
    for (int e = 0; e < TE; e++)
        acc = fmaf(p_s[e], encb[(size_t)e * HH + tid], acc);
    c_out[((size_t)b * TD + d) * HH + tid] = acc;
}

// ---------------------------------------------------------------------------
extern "C" void kernel_launch(void* const* d_in, const int* in_sizes, int n_in,
                              void* d_out, int out_size) {
    const float* enc = (const float*)d_in[0];   // [16,128,256]
    const float* dec = (const float*)d_in[1];   // [16,128,256]
    const float* Wa  = (const float*)d_in[2];   // [256,256]
    const float* Ua  = (const float*)d_in[3];   // [256,256]
    const float* Va  = (const float*)d_in[4];   // [256,1]

    float* c_out = (float*)d_out;                          // [16,128,256]
    float* e_out = (float*)d_out + (size_t)BB * TD * HH;   // [16,128,128]

    // 1) orthogonalize
    ortho_kernel<<<(BB * HH + 255) / 256, 256>>>(enc);

    // 2) was = enc@Wa, uah = dec@Ua  (batched in z)
    dim3 ggrid(HH / GBN, (BB * TE) / GBM, 2);   // (4, 32, 2)
    gemm_batch_kernel<<<ggrid, 256>>>(dec, Wa, Ua);

    // 3) fused energy + softmax + context
    dim3 agrid(TD, BB);
    attn_kernel<<<agrid, 256>>>(Va, c_out, e_out);
}

// round 3
// speedup vs baseline: 1.4920x; 1.4920x over previous
#include <cuda_runtime.h>
#include <math.h>

#define BB 16
#define TE 128
#define TD 128
#define HH 256
#define OCH 16            // ortho t-chunk size
#define NCH (TE / OCH)    // 8 chunks
#define DTILE 8           // decoder positions per attn block

// Scratch (device globals — no dynamic allocation allowed)
__device__ float g_enc[BB * TE * HH];   // orthogonalized encoder
__device__ float g_was[BB * TE * HH];   // enc @ W_a
__device__ float g_uah[BB * TD * HH];   // dec @ U_a

__device__ __forceinline__ float tanh_fast(float x) {
    float y;
    asm("tanh.approx.f32 %0, %1;" : "=f"(y) : "f"(x));
    return y;
}

// ---------------------------------------------------------------------------
// Kernel 1: orthogonalize, chunk-parallel.
// Block (chunk c, batch b), 256 threads = h. Each thread:
//   1) prefix-sums rows [0, c*OCH) in ascending order (same FP order as ref)
//   2) scans its OCH rows: out = x - ((x*s)/(x*x))*x ; s += x
// 128 blocks instead of 16; prefix loop is load-parallel (no div chain).
// ---------------------------------------------------------------------------
__global__ void ortho_kernel(const float* __restrict__ enc_in) {
    int c = blockIdx.x;
    int b = blockIdx.y;
    int h = threadIdx.x;
    const float* src = enc_in + (size_t)b * TE * HH + h;
    float* dst = g_enc + (size_t)b * TE * HH + h;

    int t0 = c * OCH;
    float s = 0.0f;
    #pragma unroll 8
    for (int t = 0; t < t0; t++)
        s += src[(size_t)t * HH];

    const float* sp = src + (size_t)t0 * HH;
    float* dp = dst + (size_t)t0 * HH;
    #pragma unroll
    for (int t = 0; t < OCH; t++) {
        float x = sp[(size_t)t * HH];
        float o = x - __fdividef(x * s, x * x) * x;   // t0=0,t=0: s=0 -> o=x
        dp[(size_t)t * HH] = o;
        s += x;
    }
}

// ---------------------------------------------------------------------------
// Kernel 2: batched SGEMM.  z=0: g_was = g_enc @ W ;  z=1: g_uah = dec @ U
// M=2048, N=256, K=256. 64x64 tile, BK=16, 256 threads, 4x4 per-thread tile.
// ---------------------------------------------------------------------------
#define GBM 64
#define GBN 64
#define GBK 16
__global__ void gemm_batch_kernel(const float* __restrict__ dec,
                                  const float* __restrict__ W,
                                  const float* __restrict__ U) {
    const float* A;
    const float* Bm;
    float* C;
    if (blockIdx.z == 0) { A = g_enc; Bm = W; C = g_was; }
    else                 { A = dec;   Bm = U; C = g_uah; }

    const int N = HH;        // 256
    const int K = HH;        // 256

    __shared__ float As[GBK][GBM];
    __shared__ float Bs[GBK][GBN];

    int tid = threadIdx.x;
    int tx = tid % 16;        // col group
    int ty = tid / 16;        // row group
    int row0 = blockIdx.y * GBM;
    int col0 = blockIdx.x * GBN;

    float acc[4][4] = {};

    for (int k0 = 0; k0 < K; k0 += GBK) {
        #pragma unroll
        for (int i = tid; i < GBM * GBK; i += 256) {
            int r = i / GBK, c = i % GBK;
            As[c][r] = A[(size_t)(row0 + r) * K + k0 + c];
        }
        #pragma unroll
        for (int i = tid; i < GBK * GBN; i += 256) {
            int r = i / GBN, c = i % GBN;
            Bs[r][c] = Bm[(size_t)(k0 + r) * N + col0 + c];
        }
        __syncthreads();

        #pragma unroll
        for (int k = 0; k < GBK; k++) {
            float a[4], bv[4];
            #pragma unroll
            for (int m = 0; m < 4; m++) a[m] = As[k][ty * 4 + m];
            #pragma unroll
            for (int n = 0; n < 4; n++) bv[n] = Bs[k][tx * 4 + n];
            #pragma unroll
            for (int m = 0; m < 4; m++)
                #pragma unroll
                for (int n = 0; n < 4; n++)
                    acc[m][n] = fmaf(a[m], bv[n], acc[m][n]);
        }
        __syncthreads();
    }

    #pragma unroll
    for (int m = 0; m < 4; m++)
        #pragma unroll
        for (int n = 0; n < 4; n++)
            C[(size_t)(row0 + ty * 4 + m) * N + col0 + tx * 4 + n] = acc[m][n];
}

// ---------------------------------------------------------------------------
// Kernel 3: fused energy + softmax + context, DTILE=8 decoder positions/block.
// Block (d-tile, b), 256 threads = 8 warps.
//   Phase B: warp w handles energies for e = w, w+8, ...; each was/V load is
//            reused across all 8 d's in registers (8x less L2 traffic).
//   Phase C: warp w owns softmax for d = d0 + w (warp-local reductions only).
//   Phase D: thread h accumulates 8 contexts; enc row loaded once per e.
// ---------------------------------------------------------------------------
__global__ void attn_kernel(const float* __restrict__ Va,
                            float* __restrict__ c_out,
                            float* __restrict__ e_out) {
    int d0 = blockIdx.x * DTILE;
    int b = blockIdx.y;
    int tid = threadIdx.x;
    int lane = tid & 31;
    int wid = tid >> 5;

    __shared__ float uah_s[DTILE][HH];
    __shared__ float V_s[HH];
    __shared__ float en_s[DTILE][TE];
    __shared__ float p_s[DTILE][TE];

    #pragma unroll
    for (int i = tid; i < DTILE * HH; i += 256) {
        int dt = i / HH, h = i % HH;
        uah_s[dt][h] = g_uah[((size_t)b * TD + d0 + dt) * HH + h];
    }
    V_s[tid] = Va[tid];
    __syncthreads();

    const float* wasb = g_was + (size_t)b * TE * HH;

    // ---- Phase B: energies for 8 d's at once ----
    for (int e = wid; e < TE; e += 8) {
        const float* wrow = wasb + (size_t)e * HH;
        float acc[DTILE];
        #pragma unroll
        for (int dt = 0; dt < DTILE; dt++) acc[dt] = 0.0f;

        #pragma unroll
        for (int i = 0; i < 8; i++) {
            int h = lane + 32 * i;
            float w = wrow[h];
            float v = V_s[h];
            #pragma unroll
            for (int dt = 0; dt < DTILE; dt++)
                acc[dt] = fmaf(tanh_fast(w + uah_s[dt][h]), v, acc[dt]);
        }
        #pragma unroll
        for (int dt = 0; dt < DTILE; dt++) {
            float a = acc[dt];
            #pragma unroll
            for (int o = 16; o > 0; o >>= 1)
                a += __shfl_xor_sync(0xffffffffu, a, o);
            if (lane == 0) en_s[dt][e] = a;
        }
    }
    __syncthreads();

    // ---- Phase C: softmax, warp wid owns d = d0 + wid ----
    {
        int dt = wid;
        float v[4];
        #pragma unroll
        for (int i = 0; i < 4; i++) v[i] = en_s[dt][lane + 32 * i];
        float m = fmaxf(fmaxf(v[0], v[1]), fmaxf(v[2], v[3]));
        #pragma unroll
        for (int o = 16; o > 0; o >>= 1)
            m = fmaxf(m, __shfl_xor_sync(0xffffffffu, m, o));
        float p[4];
        float s = 0.0f;
        #pragma unroll
        for (int i = 0; i < 4; i++) { p[i] = __expf(v[i] - m); s += p[i]; }
        #pragma unroll
        for (int o = 16; o > 0; o >>= 1)
            s += __shfl_xor_sync(0xffffffffu, s, o);
        float inv = __fdividef(1.0f, s);
        float* eo = e_out + ((size_t)b * TD + d0 + dt) * TE;
        #pragma unroll
        for (int i = 0; i < 4; i++) {
            float pn = p[i] * inv;
            p_s[dt][lane + 32 * i] = pn;
            eo[lane + 32 * i] = pn;
        }
    }
    __syncthreads();

    // ---- Phase D: contexts for 8 d's; enc row loaded once per e ----
    const float* encb = g_enc + (size_t)b * TE * HH;
    float acc[DTILE];
    #pragma unroll
    for (int dt = 0; dt < DTILE; dt++) acc[dt] = 0.0f;
    #pragma unroll 4
    for (int e = 0; e < TE; e++) {
        float x = encb[(size_t)e * HH + tid];
        #pragma unroll
        for (int dt = 0; dt < DTILE; dt++)
            acc[dt] = fmaf(p_s[dt][e], x, acc[dt]);
    }
    #pragma unroll
    for (int dt = 0; dt < DTILE; dt++)
        c_out[((size_t)b * TD + d0 + dt) * HH + tid] = acc[dt];
}

// ---------------------------------------------------------------------------
extern "C" void kernel_launch(void* const* d_in, const int* in_sizes, int n_in,
                              void* d_out, int out_size) {
    const float* enc = (const float*)d_in[0];   // [16,128,256]
    const float* dec = (const float*)d_in[1];   // [16,128,256]
    const float* Wa  = (const float*)d_in[2];   // [256,256]
    const float* Ua  = (const float*)d_in[3];   // [256,256]
    const float* Va  = (const float*)d_in[4];   // [256,1]

    float* c_out = (float*)d_out;                          // [16,128,256]
    float* e_out = (float*)d_out + (size_t)BB * TD * HH;   // [16,128,128]

    // 1) orthogonalize (chunk-parallel, 128 blocks)
    dim3 ogrid(NCH, BB);
    ortho_kernel<<<ogrid, 256>>>(enc);

    // 2) was = enc@Wa, uah = dec@Ua  (batched in z)
    dim3 ggrid(HH / GBN, (BB * TE) / GBM, 2);   // (4, 32, 2)
    gemm_batch_kernel<<<ggrid, 256>>>(dec, Wa, Ua);

    // 3) fused energy + softmax + context (8 d's per block)
    dim3 agrid(TD / DTILE, BB);
    attn_kernel<<<agrid, 256>>>(Va, c_out, e_out);
}